// round 17
// baseline (speedup 1.0000x reference)
#include <cuda_runtime.h>
#include <cuda_bf16.h>
#include <math.h>
#include <stdint.h>

#define Bq 128
#define Sq 1024
#define Dq 512
#define Hq 512

// ---------------- scratch (device globals; no allocs allowed) ---------------
__device__ float g_inp [Bq * Hq];
__device__ float g_att [Bq * Sq];
__device__ float g_cbar_part[4][Bq * Dq];
__device__ int   g_sidx[Bq * Sq];     // compacted unmasked s-indices per b
__device__ int   g_cnt [Bq];          // unmasked count per b
__device__ __nv_bfloat16 g_w_h[Hq * Dq];
__device__ __nv_bfloat16 g_w_l[Hq * Dq];

// ---------------- smem layout for k_mma (bytes) ------------------------------
#define RS      80
#define TSZ     (128 * RS)          // 10240 per tile per buffer
#define OF_AH   0                   // [2][TSZ]
#define OF_AL   20480
#define OF_BH   40960
#define OF_BL   61440
#define OF_PRE  81920               // 512 floats
#define OF_V    83968               // 512 floats
#define OF_ATTW 86016               // 4 x 128 floats
#define SMEM_SZ 88064

// ---------------- PTX helpers ------------------------------------------------
__device__ __forceinline__ uint32_t smem_u32(const void* p) {
    uint32_t a;
    asm("{ .reg .u64 t; cvta.to.shared.u64 t, %1; cvt.u32.u64 %0, t; }"
        : "=r"(a) : "l"(p));
    return a;
}
__device__ __forceinline__ void cp16(uint32_t dst, const void* src) {
    asm volatile("cp.async.cg.shared.global [%0], [%1], 16;"
                 :: "r"(dst), "l"(src) : "memory");
}
__device__ __forceinline__ void cp_commit() {
    asm volatile("cp.async.commit_group;" ::: "memory");
}
__device__ __forceinline__ void cp_wait0() {
    asm volatile("cp.async.wait_group 0;" ::: "memory");
}
__device__ __forceinline__ void ldsm_x4(uint32_t& r0, uint32_t& r1,
                                        uint32_t& r2, uint32_t& r3,
                                        uint32_t addr) {
    asm volatile("ldmatrix.sync.aligned.m8n8.x4.shared.b16 {%0,%1,%2,%3}, [%4];"
                 : "=r"(r0), "=r"(r1), "=r"(r2), "=r"(r3) : "r"(addr));
}
__device__ __forceinline__ void mma16816(float* c, const uint32_t* a,
                                         const uint32_t* b) {
    asm volatile(
        "mma.sync.aligned.m16n8k16.row.col.f32.bf16.bf16.f32 "
        "{%0,%1,%2,%3}, {%4,%5,%6,%7}, {%8,%9}, {%0,%1,%2,%3};"
        : "+f"(c[0]), "+f"(c[1]), "+f"(c[2]), "+f"(c[3])
        : "r"(a[0]), "r"(a[1]), "r"(a[2]), "r"(a[3]), "r"(b[0]), "r"(b[1]));
}

// ---------------- fast tanh: FMA-only rational, no MUFU ----------------------
__device__ __forceinline__ float fast_tanh(float x) {
    x = fminf(fmaxf(x, -7.99881172f), 7.99881172f);
    const float x2 = x * x;
    float p = fmaf(x2, -2.76076847742355e-16f, 2.00018790482477e-13f);
    p = fmaf(p, x2, -8.60467152213735e-11f);
    p = fmaf(p, x2,  5.12229709037114e-08f);
    p = fmaf(p, x2,  1.48572235717979e-05f);
    p = fmaf(p, x2,  6.37261928875436e-04f);
    p = fmaf(p, x2,  4.89352455891786e-03f);
    p *= x;
    float q = fmaf(x2, 1.19825839466702e-06f, 1.18534705686654e-04f);
    q = fmaf(q, x2, 2.26843463243900e-03f);
    q = fmaf(q, x2, 4.89352518554385e-03f);
    float r = __uint_as_float(0x7EF311C3u - __float_as_uint(q));
    r = r * (2.0f - q * r);
    r = r * (2.0f - q * r);
    r = r * (2.0f - q * r);
    return p * r;
}

// ---------------------------------------------------------------------------
// k_compact: per-b stable compaction of unmasked s indices (ballot scan).
// ---------------------------------------------------------------------------
__global__ void k_compact(const int* __restrict__ mask) {
    const int b = blockIdx.x, tid = threadIdx.x;
    const int wid = tid >> 5, lane = tid & 31;
    __shared__ int wcnt[32];
    const int um = (mask[b * Sq + tid] == 0);
    const unsigned bal = __ballot_sync(0xffffffffu, um);
    if (lane == 0) wcnt[wid] = __popc(bal);
    __syncthreads();
    if (tid == 0) {
        int t = 0;
        for (int i = 0; i < 32; i++) { int c = wcnt[i]; wcnt[i] = t; t += c; }
        g_cnt[b] = t;
    }
    __syncthreads();
    if (um) {
        const int pos = wcnt[wid] + __popc(bal & ((1u << lane) - 1u));
        g_sidx[b * Sq + pos] = tid;
    }
}

// ---------------------------------------------------------------------------
// bf16 hi/lo split helpers
// ---------------------------------------------------------------------------
__device__ __forceinline__ uint32_t pack_bf2(float a, float b) {
    __nv_bfloat162 t;
    t.x = __float2bfloat16(a);
    t.y = __float2bfloat16(b);
    return *(uint32_t*)&t;
}
__device__ __forceinline__ void split4(float4 v, uint2& H, uint2& L) {
    float h0 = __bfloat162float(__float2bfloat16(v.x));
    float h1 = __bfloat162float(__float2bfloat16(v.y));
    float h2 = __bfloat162float(__float2bfloat16(v.z));
    float h3 = __bfloat162float(__float2bfloat16(v.w));
    H.x = pack_bf2(h0, h1);            H.y = pack_bf2(h2, h3);
    L.x = pack_bf2(v.x - h0, v.y - h1);
    L.y = pack_bf2(v.z - h2, v.w - h3);
}

__global__ void k_split_w(const float4* __restrict__ src,
                          uint2* __restrict__ dh, uint2* __restrict__ dl,
                          int n4) {
    const int i = blockIdx.x * 256 + threadIdx.x;
    if (i >= n4) return;
    uint2 H, L;
    split4(src[i], H, L);
    dh[i] = H;  dl[i] = L;
}

// ---------------------------------------------------------------------------
// k_lin: warp-per-h, lane-parallel K. grid(Bq, 4), 256 threads.
// ---------------------------------------------------------------------------
__device__ __forceinline__ void lin_body(const float* __restrict__ xs,
                                         const float* __restrict__ W,
                                         const float* __restrict__ bias,
                                         float* __restrict__ out,
                                         int b, int hc, int tid) {
    const int wid = tid >> 5, lane = tid & 31;
    for (int h = hc + wid; h < hc + 128; h += 8) {
        const float4* w = (const float4*)(W + (size_t)h * Dq) + lane * 4;
        float acc = 0.f;
#pragma unroll
        for (int i = 0; i < 4; i++) {
            float4 wv = w[i];
            const int x0 = lane * 16 + i * 4;
            acc += wv.x * xs[x0] + wv.y * xs[x0 + 1]
                 + wv.z * xs[x0 + 2] + wv.w * xs[x0 + 3];
        }
#pragma unroll
        for (int o = 16; o; o >>= 1) acc += __shfl_xor_sync(~0u, acc, o);
        if (lane == 0) out[b * Hq + h] = acc + bias[h];
    }
}

__global__ void k_lin(const float* __restrict__ X, const float* __restrict__ W,
                      const float* __restrict__ bias, float* __restrict__ out) {
    __shared__ float xs[Dq];
    const int b = blockIdx.x, hc = blockIdx.y * 128, tid = threadIdx.x;
    for (int d = tid; d < Dq; d += 256) xs[d] = X[b * Dq + d];
    __syncthreads();
    lin_body(xs, W, bias, out, b, hc, tid);
}

__global__ void k_lin_cb(const float* __restrict__ W,
                         const float* __restrict__ bias,
                         float* __restrict__ out) {
    __shared__ float xs[Dq];
    const int b = blockIdx.x, hc = blockIdx.y * 128, tid = threadIdx.x;
    for (int d = tid; d < Dq; d += 256) {
        const int i = b * Dq + d;
        xs[d] = (g_cbar_part[0][i] + g_cbar_part[1][i])
              + (g_cbar_part[2][i] + g_cbar_part[3][i]);
    }
    __syncthreads();
    lin_body(xs, W, bias, out, b, hc, tid);
}

// ---------------------------------------------------------------------------
// HMMA fused score GEMM over COMPACTED unmasked rows, with ON-THE-FLY
// fp32->bf16 hi/lo split of A (context). A path: LDG fp32 -> regs -> convert
// -> STS into the idle A buffer, hidden under the current step's MMA burst.
// B (pre-split W) stays on cp.async. grid(8, 128), 256 threads.
// ---------------------------------------------------------------------------
__global__ void __launch_bounds__(256)
k_mma(const float* __restrict__ context, const float* __restrict__ b_ctx,
      const float* __restrict__ V) {
    extern __shared__ __align__(16) char smem[];
    const int b   = blockIdx.y;
    const int s0  = blockIdx.x * 128;
    const int cnt = g_cnt[b];
    if (s0 >= cnt) return;

    const uint32_t sb = smem_u32(smem);
    const int tid  = threadIdx.x;
    const int wid  = tid >> 5;
    const int lane = tid & 31;
    const int wm   = wid & 1;
    const int wn   = wid >> 1;

    float* pre_s = (float*)(smem + OF_PRE);
    float* V_s   = (float*)(smem + OF_V);
    float* attw  = (float*)(smem + OF_ATTW);

    for (int i = tid; i < Hq; i += 256) {
        pre_s[i] = g_inp[b * Hq + i] + b_ctx[i];
        V_s[i]   = V[i];
    }

    // A: thread covers row srow (gathered), 16 fp32 of each 32-k slab
    const int srow = tid >> 1;
    const int half = tid & 1;
    const int gidx = s0 + srow < cnt ? s0 + srow : cnt - 1;
    const int grow = g_sidx[b * Sq + gidx];
    const float* pA = context + ((size_t)(b * Sq) + grow) * Dq + half * 16;
    const uint32_t aoffA = (uint32_t)(srow * RS + half * 32);   // byte off in tile

    // B: cp.async staging (pre-split W), 16B segs
    const int sseg = half * 2;
    const uint32_t sdstB = sb + (uint32_t)(srow * RS + sseg * 16);
    const __nv_bfloat16* pBh = g_w_h + (size_t)srow * Dq + sseg * 8;
    const __nv_bfloat16* pBl = g_w_l + (size_t)srow * Dq + sseg * 8;

    const uint32_t aoff = (uint32_t)((wm * 64 + (lane & 15)) * RS + (lane >> 4) * 16);
    const uint32_t boff = (uint32_t)((wn * 32 + (lane & 15)) * RS + (lane >> 4) * 16);

    float acc[4][4][4];
#pragma unroll
    for (int mi = 0; mi < 4; mi++)
#pragma unroll
        for (int nj = 0; nj < 4; nj++)
#pragma unroll
            for (int r = 0; r < 4; r++) acc[mi][nj][r] = 0.f;
    float p[8];
#pragma unroll
    for (int i = 0; i < 8; i++) p[i] = 0.f;

    float4 fA[4];
    auto ldgA = [&](int g) {
        const float4* q = (const float4*)(pA + (g & 15) * 32);
#pragma unroll
        for (int i = 0; i < 4; i++) fA[i] = q[i];
    };
    auto stsA = [&](int buf) {
        uint2 H[4], L[4];
#pragma unroll
        for (int i = 0; i < 4; i++) split4(fA[i], H[i], L[i]);
        uint4* dh = (uint4*)(smem + buf * TSZ + OF_AH + aoffA);
        uint4* dl = (uint4*)(smem + buf * TSZ + OF_AL + aoffA);
        dh[0] = make_uint4(H[0].x, H[0].y, H[1].x, H[1].y);
        dh[1] = make_uint4(H[2].x, H[2].y, H[3].x, H[3].y);
        dl[0] = make_uint4(L[0].x, L[0].y, L[1].x, L[1].y);
        dl[1] = make_uint4(L[2].x, L[2].y, L[3].x, L[3].y);
    };
    auto stageB = [&](int g, int buf) {
        const int ka = (g & 15) * 32;
        const int hb = (g >> 4) * 128;
        const uint32_t d = sdstB + (uint32_t)(buf * TSZ);
        const __nv_bfloat16* b_h = pBh + (size_t)hb * Dq + ka;
        const __nv_bfloat16* b_l = pBl + (size_t)hb * Dq + ka;
        cp16(d + OF_BH,      b_h);
        cp16(d + OF_BH + 16, b_h + 8);
        cp16(d + OF_BL,      b_l);
        cp16(d + OF_BL + 16, b_l + 8);
    };

    // prologue: A(0) converted into buf0; B(0) in flight
    ldgA(0);
    stsA(0);
    stageB(0, 0);
    cp_commit();

    for (int g = 0; g < 64; g++) {
        const int buf = g & 1;
        cp_wait0();
        __syncthreads();            // B(g) landed, A(g) STS visible
        if (g < 63) {
            ldgA(g + 1);            // LDG latency hides under MMA burst
            stageB(g + 1, buf ^ 1);
            cp_commit();
        }

        const uint32_t bo = sb + (uint32_t)(buf * TSZ);
#pragma unroll
        for (int kk = 0; kk < 2; kk++) {
            const uint32_t kb = kk * 32;
            uint32_t ah[4][4], al[4][4], bh[4][2], bl[4][2];
#pragma unroll
            for (int mi = 0; mi < 4; mi++) {
                ldsm_x4(ah[mi][0], ah[mi][1], ah[mi][2], ah[mi][3],
                        bo + OF_AH + aoff + mi * (16 * RS) + kb);
                ldsm_x4(al[mi][0], al[mi][1], al[mi][2], al[mi][3],
                        bo + OF_AL + aoff + mi * (16 * RS) + kb);
            }
#pragma unroll
            for (int ni = 0; ni < 2; ni++) {
                uint32_t r0, r1, r2, r3;
                ldsm_x4(r0, r1, r2, r3, bo + OF_BH + boff + ni * (16 * RS) + kb);
                bh[ni * 2][0] = r0;     bh[ni * 2][1] = r2;
                bh[ni * 2 + 1][0] = r1; bh[ni * 2 + 1][1] = r3;
                ldsm_x4(r0, r1, r2, r3, bo + OF_BL + boff + ni * (16 * RS) + kb);
                bl[ni * 2][0] = r0;     bl[ni * 2][1] = r2;
                bl[ni * 2 + 1][0] = r1; bl[ni * 2 + 1][1] = r3;
            }
#pragma unroll
            for (int mi = 0; mi < 4; mi++)
#pragma unroll
                for (int nj = 0; nj < 4; nj++)
                    mma16816(acc[mi][nj], ah[mi], bh[nj]);
#pragma unroll
            for (int mi = 0; mi < 4; mi++)
#pragma unroll
                for (int nj = 0; nj < 4; nj++)
                    mma16816(acc[mi][nj], ah[mi], bl[nj]);
#pragma unroll
            for (int mi = 0; mi < 4; mi++)
#pragma unroll
                for (int nj = 0; nj < 4; nj++)
                    mma16816(acc[mi][nj], al[mi], bh[nj]);
        }

        if (g < 63) stsA(buf ^ 1);  // convert A(g+1) into the idle buffer

        if ((g & 15) == 15) {
            const int hc = (g >> 4) * 128;
#pragma unroll
            for (int mi = 0; mi < 4; mi++)
#pragma unroll
                for (int nj = 0; nj < 4; nj++) {
                    const int n0 = hc + wn * 32 + nj * 8 + (lane & 3) * 2;
                    const float v0 = V_s[n0],     q0 = pre_s[n0];
                    const float v1 = V_s[n0 + 1], q1 = pre_s[n0 + 1];
                    p[mi * 2] += v0 * fast_tanh(q0 + acc[mi][nj][0])
                               + v1 * fast_tanh(q1 + acc[mi][nj][1]);
                    p[mi * 2 + 1] += v0 * fast_tanh(q0 + acc[mi][nj][2])
                                   + v1 * fast_tanh(q1 + acc[mi][nj][3]);
                    acc[mi][nj][0] = 0.f; acc[mi][nj][1] = 0.f;
                    acc[mi][nj][2] = 0.f; acc[mi][nj][3] = 0.f;
                }
        }
    }

#pragma unroll
    for (int i = 0; i < 8; i++) {
        p[i] += __shfl_xor_sync(0xffffffffu, p[i], 1);
        p[i] += __shfl_xor_sync(0xffffffffu, p[i], 2);
    }
    if ((lane & 3) == 0) {
#pragma unroll
        for (int mi = 0; mi < 4; mi++)
#pragma unroll
            for (int hf = 0; hf < 2; hf++) {
                const int row = wm * 64 + mi * 16 + (lane >> 2) + hf * 8;
                attw[wn * 128 + row] = p[mi * 2 + hf];
            }
    }
    __syncthreads();
    if (tid < 128 && s0 + tid < cnt) {
        const float a = (attw[tid] + attw[128 + tid])
                      + (attw[256 + tid] + attw[384 + tid]);
        g_att[b * Sq + g_sidx[b * Sq + s0 + tid]] = a;
    }
}

// ---------------------------------------------------------------------------
// Masked softmax (mask int32).
// ---------------------------------------------------------------------------
__global__ void k_softmax(const int* __restrict__ mask,
                          float* __restrict__ alpha) {
    const int b = blockIdx.x, tid = threadIdx.x;
    __shared__ float red[8];
    float v[4];
#pragma unroll
    for (int i = 0; i < 4; i++) {
        const int s = tid + i * 256;
        const float a = g_att[b * Sq + s];
        v[i] = mask[b * Sq + s] ? -INFINITY : a;
    }
    float m = fmaxf(fmaxf(v[0], v[1]), fmaxf(v[2], v[3]));
#pragma unroll
    for (int o = 16; o; o >>= 1) m = fmaxf(m, __shfl_xor_sync(~0u, m, o));
    if ((tid & 31) == 0) red[tid >> 5] = m;
    __syncthreads();
    m = red[0];
#pragma unroll
    for (int i = 1; i < 8; i++) m = fmaxf(m, red[i]);
    __syncthreads();
    float e[4], sum = 0.f;
#pragma unroll
    for (int i = 0; i < 4; i++) { e[i] = expf(v[i] - m); sum += e[i]; }
#pragma unroll
    for (int o = 16; o; o >>= 1) sum += __shfl_xor_sync(~0u, sum, o);
    if ((tid & 31) == 0) red[tid >> 5] = sum;
    __syncthreads();
    sum = 0.f;
#pragma unroll
    for (int i = 0; i < 8; i++) sum += red[i];
    const float inv = 1.f / sum;
#pragma unroll
    for (int i = 0; i < 4; i++)
        alpha[b * Sq + tid + i * 256] = e[i] * inv;
}

// ---------------------------------------------------------------------------
// c_bar partials over LIVE rows only.
// ---------------------------------------------------------------------------
__global__ void k_cbar(const float* __restrict__ context,
                       const float* __restrict__ alpha) {
    const int b   = blockIdx.z;
    const int sc  = blockIdx.y;
    const int d   = blockIdx.x * 256 + threadIdx.x;
    const int cnt = g_cnt[b];
    const int n   = (cnt + 3) >> 2;
    const int i0  = sc * n;
    const int iN  = min(cnt - i0, n) > 0 ? min(cnt - i0, n) : 0;

    __shared__ float al[256];
    __shared__ int   ix[256];
    if ((int)threadIdx.x < iN) {
        const int s = g_sidx[b * Sq + i0 + threadIdx.x];
        ix[threadIdx.x] = s;
        al[threadIdx.x] = alpha[b * Sq + s];
    }
    __syncthreads();

    const float* cp = context + (size_t)b * Sq * Dq + d;
    float a0 = 0.f, a1 = 0.f;
    int j = 0;
    for (; j + 1 < iN; j += 2) {
        a0 += al[j]     * cp[(size_t)ix[j]     * Dq];
        a1 += al[j + 1] * cp[(size_t)ix[j + 1] * Dq];
    }
    if (j < iN) a0 += al[j] * cp[(size_t)ix[j] * Dq];
    g_cbar_part[sc][b * Dq + d] = a0 + a1;
}

// ---------------------------------------------------------------------------
extern "C" void kernel_launch(void* const* d_in, const int* in_sizes, int n_in,
                              void* d_out, int out_size) {
    const float* input   = (const float*)d_in[0];
    const float* context = (const float*)d_in[1];
    const int*   mask    = (const int*)d_in[2];
    const float* W_in    = (const float*)d_in[3];
    const float* b_in    = (const float*)d_in[4];
    const float* W_ctx   = (const float*)d_in[5];
    const float* b_ctx   = (const float*)d_in[6];
    const float* V       = (const float*)d_in[7];

    float* hidden = (float*)d_out;
    float* alpha  = (float*)d_out + Bq * Hq;

    float* p_inp = nullptr;
    void  *p_wh = nullptr, *p_wl = nullptr;
    cudaGetSymbolAddress((void**)&p_inp, g_inp);
    cudaGetSymbolAddress(&p_wh, g_w_h);
    cudaGetSymbolAddress(&p_wl, g_w_l);

    cudaFuncSetAttribute(k_mma, cudaFuncAttributeMaxDynamicSharedMemorySize,
                         SMEM_SZ);

    const int n4w = Hq * Dq / 4;
    k_compact<<<Bq, 1024>>>(mask);
    k_split_w<<<n4w / 256, 256>>>((const float4*)W_ctx,
                                  (uint2*)p_wh, (uint2*)p_wl, n4w);
    k_lin    <<<dim3(Bq, 4), 256>>>(input, W_in, b_in, p_inp);
    k_mma    <<<dim3(Sq / 128, Bq), 256, SMEM_SZ>>>(context, b_ctx, V);
    k_softmax<<<Bq, 256>>>(mask, alpha);
    k_cbar   <<<dim3(2, 4, Bq), 256>>>(context, alpha);
    k_lin_cb <<<dim3(Bq, 4), 256>>>(W_ctx, b_ctx, hidden);
}